// round 16
// baseline (speedup 1.0000x reference)
#include <cuda_runtime.h>
#include <cuda_fp16.h>
#include <cstdint>

// ---------------- problem constants ----------------
#define NB 64          // batch
#define NSQ 16         // steps
#define NO 31          // real opcodes
#define NOP 32         // padded opcode slots
#define ND 1024        // hidden dim
#define NOG 4          // opcodes per GEMM CTA
#define OGRP 8         // CTA opcode groups
#define NGRP 16        // output partial groups (8 CTA-groups x 2 warp op-halves)

// ---------------- GEMM tiling ----------------
#define GN 64                  // N per CTA (-> 128B contiguous gmem chunks)
#define GK 64                  // d-values per stage
#define STAGES 4
#define NIT (ND / GK)          // 16 k-stages
#define GEMM_THREADS 512       // 16 warps: 2 (op-half) x 2 (M) x 4 (N16)

#define ROWB 144                    // padded smem row stride (bank-spread)
#define B_OP_BYTES (GK * ROWB)      // 9216 per op per stage
#define BBYTES (NOG * B_OP_BYTES)   // 36864
#define ABYTES (GK * ROWB)          // 9216 (64 b-rows x 128B data)
#define STAGE_BYTES (BBYTES + ABYTES)     // 46080
#define STAGE_TX (320 * 128)              // 40960 bytes transferred per stage
#define SMEM_TOTAL (1024 + STAGES * STAGE_BYTES)   // 185344

// ---------------- device scratch (static; allocation is forbidden) ------------
// g_Kh: K converted to fp16, SAME layout as input: [o][d][n]  (slot 31 zero)
__device__ __align__(256) __half g_Kh[(size_t)NOP * ND * ND];  // 64 MB
__device__ __align__(256) __half g_H[NB * ND];                 // fp16 h (A operand)
__device__ __align__(256) float  g_h[NB * ND];                 // fp32 master h
__device__ __align__(256) float  g_w[NSQ * NB * NOP];          // softmax weights
__device__ __align__(256) float  g_gate[NSQ * NB];             // sigmoid(gate)
__device__ __align__(256) float  g_P[(size_t)NGRP * NB * ND];  // partials, 4 MB

// ---------------- PTX helpers ----------------
__device__ __forceinline__ uint32_t smem_u32(const void* p) {
    uint32_t a;
    asm("{ .reg .u64 t; cvta.to.shared.u64 t, %1; cvt.u32.u64 %0, t; }" : "=r"(a) : "l"(p));
    return a;
}
// 128-byte bulk copy global->shared, completion via mbarrier tx-bytes
__device__ __forceinline__ void bulk128(uint32_t dst, const void* src, uint32_t mbar) {
    asm volatile(
        "cp.async.bulk.shared::cta.global.mbarrier::complete_tx::bytes [%0], [%1], 128, [%2];"
        :: "r"(dst), "l"((unsigned long long)__cvta_generic_to_global(src)), "r"(mbar)
        : "memory");
}
#define MBAR_INIT(mbar) \
    asm volatile("mbarrier.init.shared.b64 [%0], 1;" :: "r"((uint32_t)(mbar)) : "memory")
#define MBAR_EXPECT(mbar, bytes) \
    asm volatile("mbarrier.arrive.expect_tx.shared.b64 _, [%0], %1;" \
                 :: "r"((uint32_t)(mbar)), "r"((uint32_t)(bytes)) : "memory")
#define MBAR_WAIT(mbar, parity) do { \
    uint32_t _m = (uint32_t)(mbar); uint32_t _p = (uint32_t)(parity); uint32_t _d; \
    asm volatile( \
        "{\n\t.reg .pred p;\n\t" \
        "mbarrier.try_wait.parity.acquire.cta.shared::cta.b64 p, [%1], %2;\n\t" \
        "selp.b32 %0, 1, 0, p;\n\t}" : "=r"(_d) : "r"(_m), "r"(_p) : "memory"); \
    if (!_d) { \
        asm volatile( \
            "{\n\t.reg .pred P1;\n\t" \
            "WL_%=:\n\t" \
            "mbarrier.try_wait.parity.acquire.cta.shared::cta.b64 P1, [%0], %1, 0x989680;\n\t" \
            "@P1 bra.uni WD_%=;\n\t" \
            "bra.uni WL_%=;\n\t" \
            "WD_%=:\n\t}" :: "r"(_m), "r"(_p) : "memory"); \
    } \
} while (0)

__device__ __forceinline__ void ldm_x4(uint32_t& r0, uint32_t& r1, uint32_t& r2,
                                       uint32_t& r3, uint32_t addr) {
    asm volatile("ldmatrix.sync.aligned.m8n8.x4.shared.b16 {%0,%1,%2,%3}, [%4];"
                 : "=r"(r0), "=r"(r1), "=r"(r2), "=r"(r3) : "r"(addr));
}
__device__ __forceinline__ void ldm_x4_trans(uint32_t& r0, uint32_t& r1, uint32_t& r2,
                                             uint32_t& r3, uint32_t addr) {
    asm volatile("ldmatrix.sync.aligned.m8n8.x4.trans.shared.b16 {%0,%1,%2,%3}, [%4];"
                 : "=r"(r0), "=r"(r1), "=r"(r2), "=r"(r3) : "r"(addr));
}
__device__ __forceinline__ void mma16816(float* c, uint32_t a0, uint32_t a1,
                                         uint32_t a2, uint32_t a3,
                                         uint32_t b0, uint32_t b1) {
    asm volatile(
        "mma.sync.aligned.m16n8k16.row.col.f32.f16.f16.f32 "
        "{%0,%1,%2,%3}, {%4,%5,%6,%7}, {%8,%9}, {%0,%1,%2,%3};"
        : "+f"(c[0]), "+f"(c[1]), "+f"(c[2]), "+f"(c[3])
        : "r"(a0), "r"(a1), "r"(a2), "r"(a3), "r"(b0), "r"(b1));
}

// ============================================================================
// Kernel 1: pure streaming convert  K fp32 -> g_Kh fp16 (identical layout).
// ============================================================================
__global__ void kconv_kernel(const float* __restrict__ K) {
    const size_t chunk = (size_t)blockIdx.x * 256 + threadIdx.x;
    const int o = (int)(chunk >> 17);
    const size_t base8 = chunk * 8;
    uint4 outv;
    if (o < NO) {
        const float4* src = reinterpret_cast<const float4*>(K + base8);
        float4 v0 = src[0];
        float4 v1 = src[1];
        __half2 h0 = __floats2half2_rn(v0.x, v0.y);
        __half2 h1 = __floats2half2_rn(v0.z, v0.w);
        __half2 h2 = __floats2half2_rn(v1.x, v1.y);
        __half2 h3 = __floats2half2_rn(v1.z, v1.w);
        outv.x = *reinterpret_cast<uint32_t*>(&h0);
        outv.y = *reinterpret_cast<uint32_t*>(&h1);
        outv.z = *reinterpret_cast<uint32_t*>(&h2);
        outv.w = *reinterpret_cast<uint32_t*>(&h3);
    } else {
        outv = make_uint4(0, 0, 0, 0);
    }
    *reinterpret_cast<uint4*>(g_Kh + base8) = outv;
}

// ============================================================================
// Kernel 2: precompute softmax weights + gates for ALL steps.
// ============================================================================
__global__ void prep_kernel(const float* __restrict__ logits,
                            const float* __restrict__ operands) {
    const int b = blockIdx.x;
    const int tid = threadIdx.x;
#pragma unroll 1
    for (int s = 0; s < NSQ; s++) {
        float l = (tid < NO) ? logits[(b * NSQ + s) * NO + tid] : -1e30f;
        float m = l;
#pragma unroll
        for (int off = 16; off; off >>= 1)
            m = fmaxf(m, __shfl_xor_sync(0xffffffff, m, off));
        float e = (tid < NO) ? expf(l - m) : 0.0f;
        float sm = e;
#pragma unroll
        for (int off = 16; off; off >>= 1)
            sm += __shfl_xor_sync(0xffffffff, sm, off);
        g_w[(s * NB + b) * NOP + tid] = e / sm;   // slot 31 -> 0
        if (tid == 0)
            g_gate[s * NB + b] =
                1.0f / (1.0f + expf(-operands[(b * NSQ + s) * 4 + 3]));
    }
}

// ============================================================================
// Kernel 3: update.  grid 256 x 128, one float2 slice per thread.
// ============================================================================
__global__ void u_kernel(const float* __restrict__ signal,
                         float* __restrict__ out, int t) {
    const int g  = blockIdx.x * 128 + threadIdx.x;
    const int b  = g >> 9;
    const int d2 = g & 511;

    float2 hv;
    if (t == 0) {
        hv = reinterpret_cast<const float2*>(signal)[b * 512 + d2];
    } else {
        const float s  = g_gate[(t - 1) * NB + b];
        const float is = 1.0f - s;
        float2 acc = make_float2(0.f, 0.f);
        const float2* P2 = reinterpret_cast<const float2*>(g_P);
#pragma unroll
        for (int gr = 0; gr < NGRP; gr++) {
            float2 p = P2[((size_t)gr * NB + b) * 512 + d2];
            acc.x += p.x; acc.y += p.y;
        }
        float2 ho = reinterpret_cast<const float2*>(g_h)[b * 512 + d2];
        hv.x = s * acc.x + is * ho.x;
        hv.y = s * acc.y + is * ho.y;
    }

    if (t < NSQ) {
        reinterpret_cast<float2*>(g_h)[b * 512 + d2] = hv;
        __half2 hh = __floats2half2_rn(hv.x, hv.y);
        reinterpret_cast<__half2*>(g_H)[b * 512 + d2] = hh;
    } else {
        reinterpret_cast<float2*>(out)[b * 512 + d2] = hv;
    }
}

// ============================================================================
// Kernel 4: GEMM.  grid (16 n-tiles, 8 op-groups), 512 threads, ~181 KB smem.
// cp.async.bulk 128B chunks (320/stage vs 2560 cp16 in R14 — targets the
// LDGSTS-issue bottleneck).  Stride-144 padded rows -> conflict-free ldmatrix.
//   P[og*2+wo][b][n] = sum_{2 ops} w[b,op] * sum_d H[b,d] * K[op,d,n]
// Hardening vs R15: expect_tx is globally ordered BEFORE all producer issues
// of the same epoch via __syncthreads().
// ============================================================================
__global__ void __launch_bounds__(GEMM_THREADS, 1) gemm_kernel(int t) {
    extern __shared__ char smem_raw[];
    const uint32_t sb = (smem_u32(smem_raw) + 1023u) & ~1023u;
    const int tid  = threadIdx.x;
    const int lane = tid & 31;
    const int wid  = tid >> 5;
    const int wn   = wid & 3;          // N 16-col slice
    const int wm   = (wid >> 2) & 1;   // M 32-half
    const int wo   = wid >> 3;         // op half: local ops wo*2, wo*2+1
    const int og   = blockIdx.y;       // 0..7
    const int n0   = blockIdx.x * GN;  // 0..960

    const __half* Ksrc = g_Kh + ((size_t)(og * NOG) << 20);

    // mbarrier init (4 slots at sb + s*8) + pre-arm expects for prologue slots
    if (tid == 0) {
#pragma unroll
        for (int s = 0; s < STAGES; s++) MBAR_INIT(sb + s * 8);
    }
    __syncthreads();

    // copies only (no expect) — expect is armed separately before issue
    auto copies = [&](int s) {
        const int slot = s & (STAGES - 1);
        const uint32_t mbar  = sb + slot * 8;
        const uint32_t stage = sb + 1024 + slot * STAGE_BYTES;
        const int kk = s * GK;
        if (tid < 256) {                      // B: 4 ops x 64 d-rows
            const int op = tid >> 6, d = tid & 63;
            bulk128(stage + op * B_OP_BYTES + d * ROWB,
                    (const char*)(Ksrc + ((size_t)op << 20) +
                                  (size_t)(kk + d) * ND + n0),
                    mbar);
        } else if (tid < 320) {               // A: 64 b-rows
            const int r = tid - 256;
            bulk128(stage + BBYTES + r * ROWB,
                    (const char*)(g_H + (size_t)r * ND + kk),
                    mbar);
        }
    };

    float acc[2][2][2][4];   // [opl][mi][ng][4]
#pragma unroll
    for (int o = 0; o < 2; o++)
#pragma unroll
        for (int mi = 0; mi < 2; mi++)
#pragma unroll
            for (int ng = 0; ng < 2; ng++)
#pragma unroll
                for (int c = 0; c < 4; c++) acc[o][mi][ng][c] = 0.0f;

    // prologue: arm expects for slots 0..2, sync, then issue copies
    if (tid == 0) {
        MBAR_EXPECT(sb + 0 * 8, STAGE_TX);
        MBAR_EXPECT(sb + 1 * 8, STAGE_TX);
        MBAR_EXPECT(sb + 2 * 8, STAGE_TX);
    }
    __syncthreads();
    copies(0); copies(1); copies(2);

    const int lq   = lane & 15;         // row selector within matrix pair
    const int lh16 = (lane >> 4) * 16;  // 0 / 16B: second matrix pair

#pragma unroll 1
    for (int j = 0; j < NIT; j++) {
        MBAR_WAIT(sb + (j & 3) * 8, (j >> 2) & 1);
        // arm expect for the refill slot BEFORE the sync that precedes issues
        const int jr = j + STAGES - 1;
        if (tid == 0 && jr < NIT) MBAR_EXPECT(sb + (jr & 3) * 8, STAGE_TX);
        __syncthreads();     // all warps done with slot (j-1)&3; expect armed
        if (jr < NIT) copies(jr);

        const uint32_t stage = sb + 1024 + (j & 3) * STAGE_BYTES;
        const uint32_t abase = stage + BBYTES;
        const uint32_t bopb  = stage + (wo * 2) * B_OP_BYTES;
#pragma unroll
        for (int kc = 0; kc < 4; kc++) {
            uint32_t a[2][4];
#pragma unroll
            for (int mi = 0; mi < 2; mi++) {
                const int row = wm * 32 + mi * 16 + lq;
                ldm_x4(a[mi][0], a[mi][1], a[mi][2], a[mi][3],
                       abase + row * ROWB + kc * 32 + lh16);
            }
            const uint32_t boff = (kc * 16 + lq) * ROWB + wn * 32 + lh16;
#pragma unroll
            for (int opl = 0; opl < 2; opl++) {
                uint32_t b0, b1, b2, b3;   // ng0:{b0,b1} ng1:{b2,b3}
                ldm_x4_trans(b0, b1, b2, b3, bopb + opl * B_OP_BYTES + boff);
                mma16816(acc[opl][0][0], a[0][0], a[0][1], a[0][2], a[0][3], b0, b1);
                mma16816(acc[opl][1][0], a[1][0], a[1][1], a[1][2], a[1][3], b0, b1);
                mma16816(acc[opl][0][1], a[0][0], a[0][1], a[0][2], a[0][3], b2, b3);
                mma16816(acc[opl][1][1], a[1][0], a[1][1], a[1][2], a[1][3], b2, b3);
            }
        }
    }

    // ---- epilogue: fold step-t softmax weights (this warp's 2 ops) ----
    const int go = og * 2 + wo;                    // output group 0..15
    const float* wt = g_w + (size_t)t * NB * NOP + og * NOG + wo * 2;
#pragma unroll
    for (int mi = 0; mi < 2; mi++) {
        const int rA = wm * 32 + mi * 16 + (lane >> 2);
        const int rB = rA + 8;
        const float2 wA = *reinterpret_cast<const float2*>(wt + rA * NOP);
        const float2 wB = *reinterpret_cast<const float2*>(wt + rB * NOP);
#pragma unroll
        for (int ng = 0; ng < 2; ng++) {
            const int col = n0 + wn * 16 + ng * 8 + (lane & 3) * 2;
            float2 sA, sB;
            sA.x = wA.x * acc[0][mi][ng][0] + wA.y * acc[1][mi][ng][0];
            sA.y = wA.x * acc[0][mi][ng][1] + wA.y * acc[1][mi][ng][1];
            sB.x = wB.x * acc[0][mi][ng][2] + wB.y * acc[1][mi][ng][2];
            sB.y = wB.x * acc[0][mi][ng][3] + wB.y * acc[1][mi][ng][3];
            *reinterpret_cast<float2*>(g_P + ((size_t)go * NB + rA) * ND + col) = sA;
            *reinterpret_cast<float2*>(g_P + ((size_t)go * NB + rB) * ND + col) = sB;
        }
    }
}

// ============================================================================
// Launch
// ============================================================================
extern "C" void kernel_launch(void* const* d_in, const int* in_sizes, int n_in,
                              void* d_out, int out_size) {
    const float* logits   = (const float*)d_in[0];  // (64,16,31)
    const float* operands = (const float*)d_in[1];  // (64,16,4)
    const float* signal   = (const float*)d_in[2];  // (64,1024)
    const float* kernels  = (const float*)d_in[3];  // (31,1024,1024)
    float* out = (float*)d_out;                     // (64,1024)

    static bool attr_set = false;
    if (!attr_set) {
        cudaFuncSetAttribute(gemm_kernel, cudaFuncAttributeMaxDynamicSharedMemorySize,
                             SMEM_TOTAL);
        attr_set = true;
    }

    kconv_kernel<<<16384, 256>>>(kernels);
    prep_kernel<<<NB, 32>>>(logits, operands);
    for (int t = 0; t <= NSQ; t++) {
        u_kernel<<<256, 128>>>(signal, out, t);
        if (t < NSQ)
            gemm_kernel<<<dim3(16, OGRP), GEMM_THREADS, SMEM_TOTAL>>>(t);
    }
}